// round 1
// baseline (speedup 1.0000x reference)
#include <cuda_runtime.h>

static constexpr int N    = 1024;
static constexpr int EMAX = 524288;

// ---------------- device scratch (static: no allocations allowed) ----------
__device__ int   g_is64;
__device__ int   g_deg[N];
__device__ int   g_off[N + 1];
__device__ int   g_wpos[N];
__device__ int   g_src[EMAX];
__device__ float g_A1[N * 64];
__device__ float g_B1[N * 64];
__device__ float g_h1[N * 128];
__device__ float g_A2[N * 64];
__device__ float g_B2[N * 64];
__device__ float g_h2[N * 512];

__device__ __forceinline__ float neg_inf() { return __int_as_float(0xff800000); }

__device__ __forceinline__ int edge_val(const void* p, long long i, int is64) {
    if (is64) return (int)((const long long*)p)[i];
    return ((const int*)p)[i];
}

// Detect whether edge_index arrived as int64 or int32 (JAX x64 may be off).
// If data is int32, interpreting pairs as int64 yields huge values unless the
// high word happens to be 0; with 64 random values in [0,1024) the
// all-high-words-zero case has probability ~0. Deterministic for fixed input.
__global__ void k_detect(const void* edges) {
    if (threadIdx.x == 0) {
        const long long* q = (const long long*)edges;
        int ok = 1;
        for (int i = 0; i < 64; i++) {
            long long v = q[i];
            if (v < 0 || v >= N) { ok = 0; break; }
        }
        g_is64 = ok;
    }
}

__global__ void k_zero() {
    int i = blockIdx.x * blockDim.x + threadIdx.x;
    if (i < N) g_deg[i] = 0;
}

__global__ void k_hist(const void* edges, int E) {
    int is64 = g_is64;
    for (int e = blockIdx.x * blockDim.x + threadIdx.x; e < E;
         e += gridDim.x * blockDim.x) {
        int d = edge_val(edges, (long long)E + e, is64);
        atomicAdd(&g_deg[d], 1);
    }
}

__global__ void k_scan() {
    __shared__ int s[N];
    int tid = threadIdx.x;
    int mydeg = g_deg[tid];
    s[tid] = mydeg;
    __syncthreads();
    for (int off = 1; off < N; off <<= 1) {
        int v = (tid >= off) ? s[tid - off] : 0;
        __syncthreads();
        s[tid] += v;
        __syncthreads();
    }
    g_off[tid + 1] = s[tid];
    if (tid == 0) g_off[0] = 0;
    g_wpos[tid] = s[tid] - mydeg;  // exclusive prefix
}

__global__ void k_scatter(const void* edges, int E) {
    int is64 = g_is64;
    for (int e = blockIdx.x * blockDim.x + threadIdx.x; e < E;
         e += gridDim.x * blockDim.x) {
        int s = edge_val(edges, e, is64);
        int d = edge_val(edges, (long long)E + e, is64);
        int pos = atomicAdd(&g_wpos[d], 1);
        g_src[pos] = s;
    }
}

// A1 = x @ W1[0:64]  + b1 ; B1 = x @ W1[64:128]
__global__ void k_pre1(const float* __restrict__ x, const float* __restrict__ W1,
                       const float* __restrict__ b1) {
    __shared__ float xr[64];
    int n = blockIdx.x, j = threadIdx.x;
    xr[j] = x[n * 64 + j];
    __syncthreads();
    float a = b1[j], b = 0.f;
#pragma unroll 8
    for (int k = 0; k < 64; k++) {
        float xv = xr[k];
        a = fmaf(xv, W1[k * 64 + j], a);
        b = fmaf(xv, W1[(64 + k) * 64 + j], b);
    }
    g_A1[n * 64 + j] = a;
    g_B1[n * 64 + j] = b;
}

// A2 = h1 @ W3[0:128] + b3 ; B2 = h1 @ W3[128:256]
__global__ void k_pre2(const float* __restrict__ W3, const float* __restrict__ b3) {
    __shared__ float hr[128];
    int n = blockIdx.x, j = threadIdx.x;
    hr[j] = g_h1[n * 128 + j];
    hr[j + 64] = g_h1[n * 128 + j + 64];
    __syncthreads();
    float a = b3[j], b = 0.f;
#pragma unroll 8
    for (int k = 0; k < 128; k++) {
        float hv = hr[k];
        a = fmaf(hv, W3[k * 64 + j], a);
        b = fmaf(hv, W3[(128 + k) * 64 + j], b);
    }
    g_A2[n * 64 + j] = a;
    g_B2[n * 64 + j] = b;
}

// Fused per-dst-node: for each edge, pre = relu(A[dst]+B[src]) (64-wide),
// m = pre @ W2 (64 x C_OUT), running column-max. One block per dst node.
// 256 threads: cgrp = tid&63 (channel lane), egrp = tid>>6 (edge group of 4).
template <int C_OUT>
__global__ void k_conv(const float* __restrict__ Avec, const float* __restrict__ Bvec,
                       const float* __restrict__ W2, const float* __restrict__ bias,
                       float* __restrict__ out) {
    constexpr int NJ = C_OUT / 64;
    constexpr int TE = 16;
    extern __shared__ float sm[];
    float* W2s  = sm;                    // 64*C_OUT
    float* pres = W2s + 64 * C_OUT;      // TE*68 (padded rows)
    float* avs  = pres + TE * 68;        // 64
    float* red  = avs + 64;              // 4*C_OUT
    int*   srcs = (int*)(red + 4 * C_OUT);  // TE

    int n = blockIdx.x, tid = threadIdx.x;
    for (int i = tid; i < 64 * C_OUT; i += 256) W2s[i] = W2[i];
    if (tid < 64) avs[tid] = Avec[n * 64 + tid];
    int beg = g_off[n], end = g_off[n + 1];

    float acc[NJ];
#pragma unroll
    for (int j = 0; j < NJ; j++) acc[j] = neg_inf();
    int cgrp = tid & 63, egrp = tid >> 6;
    __syncthreads();

    for (int t0 = beg; t0 < end; t0 += TE) {
        int cnt = min(TE, end - t0);
        if (tid < TE) srcs[tid] = (tid < cnt) ? g_src[t0 + tid] : 0;
        __syncthreads();
        for (int i = tid; i < TE * 64; i += 256) {
            int e = i >> 6, k = i & 63;
            pres[e * 68 + k] = fmaxf(avs[k] + Bvec[srcs[e] * 64 + k], 0.f);
        }
        __syncthreads();

        float dot[4][NJ];
#pragma unroll
        for (int e = 0; e < 4; e++)
#pragma unroll
            for (int j = 0; j < NJ; j++) dot[e][j] = 0.f;

#pragma unroll 8
        for (int k = 0; k < 64; k++) {
            float p0 = pres[(egrp * 4 + 0) * 68 + k];
            float p1 = pres[(egrp * 4 + 1) * 68 + k];
            float p2 = pres[(egrp * 4 + 2) * 68 + k];
            float p3 = pres[(egrp * 4 + 3) * 68 + k];
#pragma unroll
            for (int j = 0; j < NJ; j++) {
                float w = W2s[k * C_OUT + cgrp + 64 * j];
                dot[0][j] = fmaf(p0, w, dot[0][j]);
                dot[1][j] = fmaf(p1, w, dot[1][j]);
                dot[2][j] = fmaf(p2, w, dot[2][j]);
                dot[3][j] = fmaf(p3, w, dot[3][j]);
            }
        }
#pragma unroll
        for (int e = 0; e < 4; e++) {
            if (egrp * 4 + e < cnt) {
#pragma unroll
                for (int j = 0; j < NJ; j++) acc[j] = fmaxf(acc[j], dot[e][j]);
            }
        }
        __syncthreads();
    }

#pragma unroll
    for (int j = 0; j < NJ; j++) red[egrp * C_OUT + cgrp + 64 * j] = acc[j];
    __syncthreads();
    if (tid < 64) {
#pragma unroll
        for (int j = 0; j < NJ; j++) {
            int c = tid + 64 * j;
            float m = red[c];
#pragma unroll
            for (int g = 1; g < 4; g++) m = fmaxf(m, red[g * C_OUT + c]);
            out[n * C_OUT + c] = (m == neg_inf()) ? 0.f : m + bias[c];
        }
    }
}

// out[i][j] = sum_n h2[n][i]*Wr[n][j] + br[j]   (512x512, K=1024)
__global__ void k_readout(const float* __restrict__ Wr, const float* __restrict__ br,
                          float* __restrict__ out) {
    __shared__ float As[16][64];
    __shared__ float Bs[16][64];
    int i0 = blockIdx.y * 64, j0 = blockIdx.x * 64;
    int tid = threadIdx.x;
    int jt = tid & 15, it = tid >> 4;
    float c[4][4];
#pragma unroll
    for (int r = 0; r < 4; r++)
#pragma unroll
        for (int s = 0; s < 4; s++) c[r][s] = 0.f;

    for (int n0 = 0; n0 < N; n0 += 16) {
        for (int idx = tid; idx < 16 * 64; idx += 256) {
            int kk = idx >> 6, col = idx & 63;
            As[kk][col] = g_h2[(n0 + kk) * 512 + i0 + col];
            Bs[kk][col] = Wr[(n0 + kk) * 512 + j0 + col];
        }
        __syncthreads();
#pragma unroll
        for (int kk = 0; kk < 16; kk++) {
            float a[4], b[4];
#pragma unroll
            for (int r = 0; r < 4; r++) a[r] = As[kk][it * 4 + r];
#pragma unroll
            for (int s = 0; s < 4; s++) b[s] = Bs[kk][jt * 4 + s];
#pragma unroll
            for (int r = 0; r < 4; r++)
#pragma unroll
                for (int s = 0; s < 4; s++) c[r][s] = fmaf(a[r], b[s], c[r][s]);
        }
        __syncthreads();
    }
#pragma unroll
    for (int r = 0; r < 4; r++)
#pragma unroll
        for (int s = 0; s < 4; s++)
            out[(i0 + it * 4 + r) * 512 + j0 + jt * 4 + s] = c[r][s] + br[j0 + jt * 4 + s];
}

extern "C" void kernel_launch(void* const* d_in, const int* in_sizes, int n_in,
                              void* d_out, int out_size) {
    const float* x  = (const float*)d_in[0];
    const void*  ei = d_in[1];
    const float* W1 = (const float*)d_in[2];
    const float* b1 = (const float*)d_in[3];
    const float* W2 = (const float*)d_in[4];
    const float* b2 = (const float*)d_in[5];
    const float* W3 = (const float*)d_in[6];
    const float* b3 = (const float*)d_in[7];
    const float* W4 = (const float*)d_in[8];
    const float* b4 = (const float*)d_in[9];
    const float* Wr = (const float*)d_in[10];
    const float* br = (const float*)d_in[11];

    int E = in_sizes[1] / 2;
    if (E > EMAX) E = EMAX;

    float *pA1, *pB1, *pA2, *pB2, *ph1, *ph2;
    cudaGetSymbolAddress((void**)&pA1, g_A1);
    cudaGetSymbolAddress((void**)&pB1, g_B1);
    cudaGetSymbolAddress((void**)&pA2, g_A2);
    cudaGetSymbolAddress((void**)&pB2, g_B2);
    cudaGetSymbolAddress((void**)&ph1, g_h1);
    cudaGetSymbolAddress((void**)&ph2, g_h2);

    const int smem1 = (64 * 128 + 16 * 68 + 64 + 4 * 128) * 4 + 16 * 4;
    const int smem2 = (64 * 512 + 16 * 68 + 64 + 4 * 512) * 4 + 16 * 4;
    cudaFuncSetAttribute(k_conv<512>, cudaFuncAttributeMaxDynamicSharedMemorySize, smem2);
    cudaFuncSetAttribute(k_conv<128>, cudaFuncAttributeMaxDynamicSharedMemorySize, smem1);

    k_detect<<<1, 32>>>(ei);
    k_zero<<<4, 256>>>();
    k_pre1<<<N, 64>>>(x, W1, b1);
    k_hist<<<512, 256>>>(ei, E);
    k_scan<<<1, 1024>>>();
    k_scatter<<<512, 256>>>(ei, E);
    k_conv<128><<<N, 256, smem1>>>(pA1, pB1, W2, b2, ph1);
    k_pre2<<<N, 64>>>(W3, b3);
    k_conv<512><<<N, 256, smem2>>>(pA2, pB2, W4, b4, ph2);
    k_readout<<<dim3(8, 8), 256>>>(Wr, br, (float*)d_out);
}

// round 4
// speedup vs baseline: 3.6494x; 3.6494x over previous
#include <cuda_runtime.h>
#include <cstdint>

static constexpr int N    = 1024;
static constexpr int EMAX = 524288;
static constexpr int HB   = 128;   // histogram blocks

// ---------------- device scratch ----------------
__device__ int   g_is64;
__device__ int   g_bh[HB * N];
__device__ int   g_off[N + 1];
__device__ int   g_src[EMAX];
__device__ float g_A1[N * 64];
__device__ float g_B1[N * 64];
__device__ float g_h1[N * 128];
__device__ float g_A2[N * 64];
__device__ float g_B2[N * 64];
__device__ float g_h2[N * 512];

__device__ __forceinline__ float neg_inf() { return __int_as_float(0xff800000); }

__device__ __forceinline__ uint32_t f2tf(float f) {
    uint32_t u;
    asm("cvt.rna.tf32.f32 %0, %1;" : "=r"(u) : "f"(f));
    return u;
}

__device__ __forceinline__ void mma_tf32(float d[4], const uint32_t a[4],
                                         const uint32_t b[2]) {
    asm volatile(
        "mma.sync.aligned.m16n8k8.row.col.f32.tf32.tf32.f32 "
        "{%0,%1,%2,%3}, {%4,%5,%6,%7}, {%8,%9}, {%0,%1,%2,%3};"
        : "+f"(d[0]), "+f"(d[1]), "+f"(d[2]), "+f"(d[3])
        : "r"(a[0]), "r"(a[1]), "r"(a[2]), "r"(a[3]), "r"(b[0]), "r"(b[1]));
}

// ---------------- sort pipeline ----------------
__device__ __forceinline__ int edge_val(const void* p, long long i, int is64) {
    if (is64) return (int)((const long long*)p)[i];
    return ((const int*)p)[i];
}

__global__ void k_detect(const void* edges) {
    if (threadIdx.x == 0) {
        const long long* q = (const long long*)edges;
        int ok = 1;
        for (int i = 0; i < 64; i++) {
            long long v = q[i];
            if (v < 0 || v >= N) { ok = 0; break; }
        }
        g_is64 = ok;
    }
}

__global__ void k_hist2(const void* edges, int E) {
    __shared__ int h[N];
    int b = blockIdx.x, tid = threadIdx.x;
    for (int i = tid; i < N; i += 512) h[i] = 0;
    __syncthreads();
    int is64 = g_is64;
    int per = (E + HB - 1) / HB;
    int s0 = b * per, s1 = min(E, s0 + per);
    for (int e = s0 + tid; e < s1; e += 512) {
        int d = edge_val(edges, (long long)E + e, is64);
        atomicAdd(&h[d], 1);
    }
    __syncthreads();
    for (int i = tid; i < N; i += 512) g_bh[b * N + i] = h[i];
}

__global__ void k_scan2() {
    __shared__ int s[N];
    int d = threadIdx.x;
    int tot = 0;
#pragma unroll 8
    for (int b = 0; b < HB; b++) {
        int t = g_bh[b * N + d];
        g_bh[b * N + d] = tot;
        tot += t;
    }
    s[d] = tot;
    __syncthreads();
    for (int off = 1; off < N; off <<= 1) {
        int v = (d >= off) ? s[d - off] : 0;
        __syncthreads();
        s[d] += v;
        __syncthreads();
    }
    g_off[d + 1] = s[d];
    if (d == 0) g_off[0] = 0;
    int base = s[d] - tot;  // exclusive prefix for dst d
#pragma unroll 8
    for (int b = 0; b < HB; b++) g_bh[b * N + d] += base;
}

__global__ void k_scatter2(const void* edges, int E) {
    __shared__ int h[N];
    int b = blockIdx.x, tid = threadIdx.x;
    for (int i = tid; i < N; i += 512) h[i] = 0;
    __syncthreads();
    int is64 = g_is64;
    int per = (E + HB - 1) / HB;
    int s0 = b * per, s1 = min(E, s0 + per);
    for (int e = s0 + tid; e < s1; e += 512) {
        int sv = edge_val(edges, e, is64);
        int d  = edge_val(edges, (long long)E + e, is64);
        int pos = g_bh[b * N + d] + atomicAdd(&h[d], 1);
        g_src[pos] = sv;
    }
}

// ---------------- per-node A/B precompute ----------------
__global__ void k_pre1(const float* __restrict__ x, const float* __restrict__ W1,
                       const float* __restrict__ b1) {
    __shared__ float xr[64];
    int n = blockIdx.x, j = threadIdx.x;
    xr[j] = x[n * 64 + j];
    __syncthreads();
    float a = b1[j], b = 0.f;
#pragma unroll 8
    for (int k = 0; k < 64; k++) {
        float xv = xr[k];
        a = fmaf(xv, W1[k * 64 + j], a);
        b = fmaf(xv, W1[(64 + k) * 64 + j], b);
    }
    g_A1[n * 64 + j] = a;
    g_B1[n * 64 + j] = b;
}

__global__ void k_pre2(const float* __restrict__ W3, const float* __restrict__ b3) {
    __shared__ float hr[128];
    int n = blockIdx.x, j = threadIdx.x;
    hr[j] = g_h1[n * 128 + j];
    hr[j + 64] = g_h1[n * 128 + j + 64];
    __syncthreads();
    float a = b3[j], b = 0.f;
#pragma unroll 8
    for (int k = 0; k < 128; k++) {
        float hv = hr[k];
        a = fmaf(hv, W3[k * 64 + j], a);
        b = fmaf(hv, W3[(128 + k) * 64 + j], b);
    }
    g_A2[n * 64 + j] = a;
    g_B2[n * 64 + j] = b;
}

// ---------------- tensor-core (mma.sync tf32) EdgeConv ----------------
// One CTA per dst node. 512 threads = 16 warps.
// EG edge-groups x (16/EG) channel-groups; each channel-group covers NT*8 cols.
// Stage 128 edges of P = relu(A[dst]+B[src]) (64-wide, tf32 bits) in smem;
// warps run m16n8k8 tf32 MMAs over their channel slice, fold column-max with
// row-validity predicates, then shfl-reduce.
//
// m16n8k8.tf32 fragment layout (PTX ISA):
//   A: a0=[g, tig], a1=[g+8, tig], a2=[g, tig+4], a3=[g+8, tig+4]
//   B: b0=[tig, col g], b1=[tig+4, col g]
//   D: d0=[g, 2tig], d1=[g, 2tig+1], d2=[g+8, 2tig], d3=[g+8, 2tig+1]
static constexpr int PADK = 68;  // row stride in 32-bit words

template <int C_OUT, int EG>
__global__ void __launch_bounds__(512, 1)
k_conv_mma(const float* __restrict__ Avec, const float* __restrict__ Bvec,
           const float* __restrict__ W, const float* __restrict__ bias,
           float* __restrict__ out) {
    constexpr int CG = 16 / EG;
    constexpr int NT = (C_OUT / CG) / 8;
    __shared__ uint32_t Ps[128 * PADK];
    __shared__ float avs[64];
    __shared__ float red[EG * C_OUT];

    int tid = threadIdx.x, wid = tid >> 5, lane = tid & 31;
    int g = lane >> 2, tig = lane & 3;
    int cgrp = wid / EG, egrp = wid % EG;
    int cbase = cgrp * (NT * 8);
    int n = blockIdx.x;

    if (tid < 64) avs[tid] = Avec[n * 64 + tid];

    // W fragments (B operand): wf[s][t][0] = W[k=8s+tig][c], wf[s][t][1] = W[k=8s+tig+4][c]
    uint32_t wf[8][NT][2];
#pragma unroll
    for (int s = 0; s < 8; s++)
#pragma unroll
        for (int t = 0; t < NT; t++) {
            int c = cbase + t * 8 + g;
            wf[s][t][0] = f2tf(W[(s * 8 + tig) * C_OUT + c]);
            wf[s][t][1] = f2tf(W[(s * 8 + tig + 4) * C_OUT + c]);
        }

    float mx[NT][2];
#pragma unroll
    for (int t = 0; t < NT; t++) { mx[t][0] = neg_inf(); mx[t][1] = neg_inf(); }

    int beg = g_off[n], end = g_off[n + 1];
    __syncthreads();

    for (int t0 = beg; t0 < end; t0 += 128) {
        int cnt = min(128, end - t0);
        // --- build P tile (tf32 bits) ---
        {
            int e = tid >> 2;
            if (e < cnt) {
                int s = g_src[t0 + e];
                const float4* Bv = (const float4*)(Bvec + s * 64);
                const float4* Av = (const float4*)avs;
                int cb = (tid & 3) * 4;  // float4 block base
                uint32_t* row = Ps + e * PADK;
#pragma unroll
                for (int j = 0; j < 4; j++) {
                    float4 b = Bv[cb + j];
                    float4 a = Av[cb + j];
                    uint4 p;
                    p.x = f2tf(fmaxf(a.x + b.x, 0.f));
                    p.y = f2tf(fmaxf(a.y + b.y, 0.f));
                    p.z = f2tf(fmaxf(a.z + b.z, 0.f));
                    p.w = f2tf(fmaxf(a.w + b.w, 0.f));
                    *(uint4*)(row + (cb + j) * 4) = p;
                }
            }
        }
        __syncthreads();
        // --- compute ---
        for (int m = egrp; m < 8; m += EG) {
            if (m * 16 >= cnt) break;
            float d[NT][4];
#pragma unroll
            for (int t = 0; t < NT; t++) {
                d[t][0] = 0.f; d[t][1] = 0.f; d[t][2] = 0.f; d[t][3] = 0.f;
            }
#pragma unroll
            for (int s = 0; s < 8; s++) {
                const uint32_t* plo = Ps + (m * 16 + g) * PADK + s * 8 + tig;
                const uint32_t* phi = plo + 8 * PADK;
                uint32_t a[4];
                a[0] = plo[0];       // [g,    tig]
                a[1] = phi[0];       // [g+8,  tig]
                a[2] = plo[4];       // [g,    tig+4]
                a[3] = phi[4];       // [g+8,  tig+4]
#pragma unroll
                for (int t = 0; t < NT; t++) mma_tf32(d[t], a, wf[s][t]);
            }
            int r0 = m * 16 + g;
            bool v0 = r0 < cnt, v1 = (r0 + 8) < cnt;
#pragma unroll
            for (int t = 0; t < NT; t++) {
                if (v0) { mx[t][0] = fmaxf(mx[t][0], d[t][0]);
                          mx[t][1] = fmaxf(mx[t][1], d[t][1]); }
                if (v1) { mx[t][0] = fmaxf(mx[t][0], d[t][2]);
                          mx[t][1] = fmaxf(mx[t][1], d[t][3]); }
            }
        }
        __syncthreads();
    }

    // reduce across the 8 row-groups (lanes stride 4, same tig)
#pragma unroll
    for (int t = 0; t < NT; t++)
#pragma unroll
        for (int off = 4; off < 32; off <<= 1) {
            mx[t][0] = fmaxf(mx[t][0], __shfl_xor_sync(0xffffffffu, mx[t][0], off));
            mx[t][1] = fmaxf(mx[t][1], __shfl_xor_sync(0xffffffffu, mx[t][1], off));
        }

    if (EG == 1) {
        if (lane < 4) {
#pragma unroll
            for (int t = 0; t < NT; t++) {
                int c = cbase + t * 8 + 2 * tig;
                float v0 = mx[t][0], v1 = mx[t][1];
                out[n * C_OUT + c]     = (v0 == neg_inf()) ? 0.f : v0 + bias[c];
                out[n * C_OUT + c + 1] = (v1 == neg_inf()) ? 0.f : v1 + bias[c + 1];
            }
        }
    } else {
        if (lane < 4) {
#pragma unroll
            for (int t = 0; t < NT; t++) {
                int c = cbase + t * 8 + 2 * tig;
                red[egrp * C_OUT + c]     = mx[t][0];
                red[egrp * C_OUT + c + 1] = mx[t][1];
            }
        }
        __syncthreads();
        for (int c = tid; c < C_OUT; c += 512) {
            float m = red[c];
#pragma unroll
            for (int e = 1; e < EG; e++) m = fmaxf(m, red[e * C_OUT + c]);
            out[n * C_OUT + c] = (m == neg_inf()) ? 0.f : m + bias[c];
        }
    }
}

// ---------------- readout: out[i][j] = sum_n h2[n][i]*Wr[n][j] + br[j] ----------
__global__ void k_readout(const float* __restrict__ Wr, const float* __restrict__ br,
                          float* __restrict__ out) {
    __shared__ float As[16][64];
    __shared__ float Bs[16][64];
    int i0 = blockIdx.y * 64, j0 = blockIdx.x * 64;
    int tid = threadIdx.x;
    int jt = tid & 15, it = tid >> 4;
    float c[4][4];
#pragma unroll
    for (int r = 0; r < 4; r++)
#pragma unroll
        for (int s = 0; s < 4; s++) c[r][s] = 0.f;

    for (int n0 = 0; n0 < N; n0 += 16) {
        for (int idx = tid; idx < 16 * 64; idx += 256) {
            int kk = idx >> 6, col = idx & 63;
            As[kk][col] = g_h2[(n0 + kk) * 512 + i0 + col];
            Bs[kk][col] = Wr[(n0 + kk) * 512 + j0 + col];
        }
        __syncthreads();
#pragma unroll
        for (int kk = 0; kk < 16; kk++) {
            float a[4], b[4];
#pragma unroll
            for (int r = 0; r < 4; r++) a[r] = As[kk][it * 4 + r];
#pragma unroll
            for (int s = 0; s < 4; s++) b[s] = Bs[kk][jt * 4 + s];
#pragma unroll
            for (int r = 0; r < 4; r++)
#pragma unroll
                for (int s = 0; s < 4; s++) c[r][s] = fmaf(a[r], b[s], c[r][s]);
        }
        __syncthreads();
    }
#pragma unroll
    for (int r = 0; r < 4; r++)
#pragma unroll
        for (int s = 0; s < 4; s++)
            out[(i0 + it * 4 + r) * 512 + j0 + jt * 4 + s] = c[r][s] + br[j0 + jt * 4 + s];
}

extern "C" void kernel_launch(void* const* d_in, const int* in_sizes, int n_in,
                              void* d_out, int out_size) {
    const float* x  = (const float*)d_in[0];
    const void*  ei = d_in[1];
    const float* W1 = (const float*)d_in[2];
    const float* b1 = (const float*)d_in[3];
    const float* W2 = (const float*)d_in[4];
    const float* b2 = (const float*)d_in[5];
    const float* W3 = (const float*)d_in[6];
    const float* b3 = (const float*)d_in[7];
    const float* W4 = (const float*)d_in[8];
    const float* b4 = (const float*)d_in[9];
    const float* Wr = (const float*)d_in[10];
    const float* br = (const float*)d_in[11];

    int E = in_sizes[1] / 2;
    if (E > EMAX) E = EMAX;

    float *pA1, *pB1, *pA2, *pB2, *ph1, *ph2;
    cudaGetSymbolAddress((void**)&pA1, g_A1);
    cudaGetSymbolAddress((void**)&pB1, g_B1);
    cudaGetSymbolAddress((void**)&pA2, g_A2);
    cudaGetSymbolAddress((void**)&pB2, g_B2);
    cudaGetSymbolAddress((void**)&ph1, g_h1);
    cudaGetSymbolAddress((void**)&ph2, g_h2);

    k_detect<<<1, 32>>>(ei);
    k_hist2<<<HB, 512>>>(ei, E);
    k_pre1<<<N, 64>>>(x, W1, b1);
    k_scan2<<<1, 1024>>>();
    k_scatter2<<<HB, 512>>>(ei, E);
    k_conv_mma<128, 4><<<N, 512>>>(pA1, pB1, W2, b2, ph1);
    k_pre2<<<N, 64>>>(W3, b3);
    k_conv_mma<512, 1><<<N, 512>>>(pA2, pB2, W4, b4, ph2);
    k_readout<<<dim3(8, 8), 256>>>(Wr, br, (float*)d_out);
}

// round 5
// speedup vs baseline: 3.7258x; 1.0209x over previous
#include <cuda_runtime.h>
#include <cstdint>

static constexpr int N    = 1024;
static constexpr int EMAX = 524288;
static constexpr int HB   = 128;   // histogram blocks

// ---------------- device scratch ----------------
__device__ int   g_is64;
__device__ int   g_bh[HB * N];
__device__ int   g_tot[N];
__device__ int   g_base[N];
__device__ int   g_off[N + 1];
__device__ int   g_src[EMAX];
__device__ float g_A1[N * 64];
__device__ float g_B1[N * 64];
__device__ float g_h1[N * 128];
__device__ float g_A2[N * 64];
__device__ float g_B2[N * 64];
__device__ float g_h2[N * 512];

__device__ __forceinline__ float neg_inf() { return __int_as_float(0xff800000); }

__device__ __forceinline__ uint32_t f2tf(float f) {
    uint32_t u;
    asm("cvt.rna.tf32.f32 %0, %1;" : "=r"(u) : "f"(f));
    return u;
}

__device__ __forceinline__ void mma_tf32(float d[4], const uint32_t a[4],
                                         const uint32_t b[2]) {
    asm volatile(
        "mma.sync.aligned.m16n8k8.row.col.f32.tf32.tf32.f32 "
        "{%0,%1,%2,%3}, {%4,%5,%6,%7}, {%8,%9}, {%0,%1,%2,%3};"
        : "+f"(d[0]), "+f"(d[1]), "+f"(d[2]), "+f"(d[3])
        : "r"(a[0]), "r"(a[1]), "r"(a[2]), "r"(a[3]), "r"(b[0]), "r"(b[1]));
}

// ---------------- sort pipeline ----------------
__device__ __forceinline__ int edge_val(const void* p, long long i, int is64) {
    if (is64) return (int)((const long long*)p)[i];
    return ((const int*)p)[i];
}

__global__ void k_detect(const void* edges) {
    if (threadIdx.x == 0) {
        const long long* q = (const long long*)edges;
        int ok = 1;
        for (int i = 0; i < 64; i++) {
            long long v = q[i];
            if (v < 0 || v >= N) { ok = 0; break; }
        }
        g_is64 = ok;
    }
}

__global__ void k_hist2(const void* edges, int E) {
    __shared__ int h[N];
    int b = blockIdx.x, tid = threadIdx.x;
    for (int i = tid; i < N; i += 512) h[i] = 0;
    __syncthreads();
    int is64 = g_is64;
    int per = (E + HB - 1) / HB;
    int s0 = b * per, s1 = min(E, s0 + per);
    for (int e = s0 + tid; e < s1; e += 512) {
        int d = edge_val(edges, (long long)E + e, is64);
        atomicAdd(&h[d], 1);
    }
    __syncthreads();
    for (int i = tid; i < N; i += 512) g_bh[b * N + i] = h[i];
}

// per-dst exclusive scan over the HB block-histograms (16 blocks x 64 dst)
__global__ void k_scanA() {
    int d = blockIdx.x * 64 + threadIdx.x;
    int tot = 0;
#pragma unroll 8
    for (int b = 0; b < HB; b++) {
        int t = g_bh[b * N + d];
        g_bh[b * N + d] = tot;
        tot += t;
    }
    g_tot[d] = tot;
}

// scan the per-dst totals over d (single block of N threads)
__global__ void k_scanB() {
    __shared__ int s[N];
    int d = threadIdx.x;
    int tot = g_tot[d];
    s[d] = tot;
    __syncthreads();
    for (int off = 1; off < N; off <<= 1) {
        int v = (d >= off) ? s[d - off] : 0;
        __syncthreads();
        s[d] += v;
        __syncthreads();
    }
    g_off[d + 1] = s[d];
    if (d == 0) g_off[0] = 0;
    g_base[d] = s[d] - tot;   // exclusive prefix for dst d
}

__global__ void k_scatter2(const void* edges, int E) {
    __shared__ int h[N];
    int b = blockIdx.x, tid = threadIdx.x;
    for (int i = tid; i < N; i += 512) h[i] = 0;
    __syncthreads();
    int is64 = g_is64;
    int per = (E + HB - 1) / HB;
    int s0 = b * per, s1 = min(E, s0 + per);
    for (int e = s0 + tid; e < s1; e += 512) {
        int sv = edge_val(edges, e, is64);
        int d  = edge_val(edges, (long long)E + e, is64);
        int pos = g_base[d] + g_bh[b * N + d] + atomicAdd(&h[d], 1);
        g_src[pos] = sv;
    }
}

// ---------------- per-node A/B precompute ----------------
__global__ void k_pre1(const float* __restrict__ x, const float* __restrict__ W1,
                       const float* __restrict__ b1) {
    __shared__ float xr[64];
    int n = blockIdx.x, j = threadIdx.x;
    xr[j] = x[n * 64 + j];
    __syncthreads();
    float a = b1[j], b = 0.f;
#pragma unroll 8
    for (int k = 0; k < 64; k++) {
        float xv = xr[k];
        a = fmaf(xv, W1[k * 64 + j], a);
        b = fmaf(xv, W1[(64 + k) * 64 + j], b);
    }
    g_A1[n * 64 + j] = a;
    g_B1[n * 64 + j] = b;
}

__global__ void k_pre2(const float* __restrict__ W3, const float* __restrict__ b3) {
    __shared__ float hr[128];
    int n = blockIdx.x, j = threadIdx.x;
    hr[j] = g_h1[n * 128 + j];
    hr[j + 64] = g_h1[n * 128 + j + 64];
    __syncthreads();
    float a = b3[j], b = 0.f;
#pragma unroll 8
    for (int k = 0; k < 128; k++) {
        float hv = hr[k];
        a = fmaf(hv, W3[k * 64 + j], a);
        b = fmaf(hv, W3[(128 + k) * 64 + j], b);
    }
    g_A2[n * 64 + j] = a;
    g_B2[n * 64 + j] = b;
}

// ---------------- tensor-core (mma.sync tf32) EdgeConv ----------------
// One CTA per dst node, 512 threads = 16 warps.
// P tile (128 edges x 64 k, tf32 bits) stored fragment-major:
//   uint4 slot [(m*32+L)*8 + ((s+L)&7)] holds lane L's m16n8k8 A-fragment
//   {P[m16+g][8s+tig], P[m16+g+8][8s+tig], P[m16+g][8s+tig+4], P[m16+g+8][8s+tig+4]}
//   with g=L>>2, tig=L&3. (s+L)&7 rotation => conflict-free STS.128/LDS.128.
// W fragments (B operand) live in registers.
// m16n8k8.tf32 PTX layout:
//   A: a0=[g,tig] a1=[g+8,tig] a2=[g,tig+4] a3=[g+8,tig+4]
//   B: b0=[tig,col g] b1=[tig+4,col g]
//   D: d0=[g,2tig] d1=[g,2tig+1] d2=[g+8,2tig] d3=[g+8,2tig+1]
template <int C_OUT, int EG>
__global__ void __launch_bounds__(512, 1)
k_conv_mma(const float* __restrict__ Avec, const float* __restrict__ Bvec,
           const float* __restrict__ W, const float* __restrict__ bias,
           float* __restrict__ out) {
    constexpr int CG = 16 / EG;
    constexpr int NT = (C_OUT / CG) / 8;
    __shared__ __align__(16) uint4 Ps4[2048];
    __shared__ float avs[64];
    __shared__ float red[EG * C_OUT];
    __shared__ int srcs[2][128];

    int tid = threadIdx.x, wid = tid >> 5, lane = tid & 31;
    int g = lane >> 2, tig = lane & 3;
    int cgrp = wid / EG, egrp = wid % EG;
    int cbase = cgrp * (NT * 8);
    int n = blockIdx.x;

    if (tid < 64) avs[tid] = Avec[n * 64 + tid];

    // W fragments (B operand): wf[s][t][0]=W[8s+tig][c], wf[s][t][1]=W[8s+tig+4][c]
    uint32_t wf[8][NT][2];
#pragma unroll
    for (int s = 0; s < 8; s++)
#pragma unroll
        for (int t = 0; t < NT; t++) {
            int c = cbase + t * 8 + g;
            wf[s][t][0] = f2tf(W[(s * 8 + tig) * C_OUT + c]);
            wf[s][t][1] = f2tf(W[(s * 8 + tig + 4) * C_OUT + c]);
        }

    float mx[NT][2];
#pragma unroll
    for (int t = 0; t < NT; t++) { mx[t][0] = neg_inf(); mx[t][1] = neg_inf(); }

    int beg = g_off[n], end = g_off[n + 1];
    if (tid < 128) srcs[0][tid] = (beg + tid < end) ? g_src[beg + tid] : 0;
    __syncthreads();

    int buf = 0;
    for (int t0 = beg; t0 < end; t0 += 128, buf ^= 1) {
        int cnt = min(128, end - t0);
        // --- build P tile, fragment-major ---
#pragma unroll
        for (int it = 0; it < 4; it++) {
            int idx = tid + it * 512;
            int m = idx >> 8, s = (idx >> 5) & 7, L = idx & 31;
            if (m * 16 < cnt) {
                int gg = L >> 2, tt = L & 3;
                int e0 = m * 16 + gg;
                int k0 = s * 8 + tt, k1 = k0 + 4;
                const float* B0 = Bvec + srcs[buf][e0] * 64;
                const float* B1 = Bvec + srcs[buf][e0 + 8] * 64;
                float a0 = avs[k0], a1 = avs[k1];
                uint4 v;
                v.x = f2tf(fmaxf(a0 + B0[k0], 0.f));
                v.y = f2tf(fmaxf(a0 + B1[k0], 0.f));
                v.z = f2tf(fmaxf(a1 + B0[k1], 0.f));
                v.w = f2tf(fmaxf(a1 + B1[k1], 0.f));
                Ps4[(m * 32 + L) * 8 + ((s + L) & 7)] = v;
            }
        }
        __syncthreads();
        // --- compute ---
        for (int m = egrp; m < 8; m += EG) {
            if (m * 16 >= cnt) break;
            float acc4[NT][4];
#pragma unroll
            for (int t = 0; t < NT; t++) {
                acc4[t][0] = 0.f; acc4[t][1] = 0.f;
                acc4[t][2] = 0.f; acc4[t][3] = 0.f;
            }
#pragma unroll
            for (int s = 0; s < 8; s++) {
                uint4 q = Ps4[(m * 32 + lane) * 8 + ((s + lane) & 7)];
                uint32_t a[4] = {q.x, q.y, q.z, q.w};
#pragma unroll
                for (int t = 0; t < NT; t++) mma_tf32(acc4[t], a, wf[s][t]);
            }
            int r0 = m * 16 + g;
            bool v0 = r0 < cnt, v1 = (r0 + 8) < cnt;
#pragma unroll
            for (int t = 0; t < NT; t++) {
                if (v0) { mx[t][0] = fmaxf(mx[t][0], acc4[t][0]);
                          mx[t][1] = fmaxf(mx[t][1], acc4[t][1]); }
                if (v1) { mx[t][0] = fmaxf(mx[t][0], acc4[t][2]);
                          mx[t][1] = fmaxf(mx[t][1], acc4[t][3]); }
            }
        }
        // prefetch next tile's src indices
        int nt0 = t0 + 128;
        if (tid < 128 && nt0 < end)
            srcs[buf ^ 1][tid] = (nt0 + tid < end) ? g_src[nt0 + tid] : 0;
        __syncthreads();
    }

    // reduce across the 8 row-groups (lanes stride 4, same tig)
#pragma unroll
    for (int t = 0; t < NT; t++)
#pragma unroll
        for (int off = 4; off < 32; off <<= 1) {
            mx[t][0] = fmaxf(mx[t][0], __shfl_xor_sync(0xffffffffu, mx[t][0], off));
            mx[t][1] = fmaxf(mx[t][1], __shfl_xor_sync(0xffffffffu, mx[t][1], off));
        }

    if (EG == 1) {
        if (lane < 4) {
#pragma unroll
            for (int t = 0; t < NT; t++) {
                int c = cbase + t * 8 + 2 * tig;
                float v0 = mx[t][0], v1 = mx[t][1];
                out[n * C_OUT + c]     = (v0 == neg_inf()) ? 0.f : v0 + bias[c];
                out[n * C_OUT + c + 1] = (v1 == neg_inf()) ? 0.f : v1 + bias[c + 1];
            }
        }
    } else {
        if (lane < 4) {
#pragma unroll
            for (int t = 0; t < NT; t++) {
                int c = cbase + t * 8 + 2 * tig;
                red[egrp * C_OUT + c]     = mx[t][0];
                red[egrp * C_OUT + c + 1] = mx[t][1];
            }
        }
        __syncthreads();
        for (int c = tid; c < C_OUT; c += 512) {
            float m = red[c];
#pragma unroll
            for (int e = 1; e < EG; e++) m = fmaxf(m, red[e * C_OUT + c]);
            out[n * C_OUT + c] = (m == neg_inf()) ? 0.f : m + bias[c];
        }
    }
}

// ---------------- readout: out[i][j] = sum_n h2[n][i]*Wr[n][j] + br[j] ----------
__global__ void k_readout(const float* __restrict__ Wr, const float* __restrict__ br,
                          float* __restrict__ out) {
    __shared__ float As[16][64];
    __shared__ float Bs[16][64];
    int i0 = blockIdx.y * 64, j0 = blockIdx.x * 64;
    int tid = threadIdx.x;
    int jt = tid & 15, it = tid >> 4;
    float c[4][4];
#pragma unroll
    for (int r = 0; r < 4; r++)
#pragma unroll
        for (int s = 0; s < 4; s++) c[r][s] = 0.f;

    for (int n0 = 0; n0 < N; n0 += 16) {
        for (int idx = tid; idx < 16 * 64; idx += 256) {
            int kk = idx >> 6, col = idx & 63;
            As[kk][col] = g_h2[(n0 + kk) * 512 + i0 + col];
            Bs[kk][col] = Wr[(n0 + kk) * 512 + j0 + col];
        }
        __syncthreads();
#pragma unroll
        for (int kk = 0; kk < 16; kk++) {
            float a[4], b[4];
#pragma unroll
            for (int r = 0; r < 4; r++) a[r] = As[kk][it * 4 + r];
#pragma unroll
            for (int s = 0; s < 4; s++) b[s] = Bs[kk][jt * 4 + s];
#pragma unroll
            for (int r = 0; r < 4; r++)
#pragma unroll
                for (int s = 0; s < 4; s++) c[r][s] = fmaf(a[r], b[s], c[r][s]);
        }
        __syncthreads();
    }
#pragma unroll
    for (int r = 0; r < 4; r++)
#pragma unroll
        for (int s = 0; s < 4; s++)
            out[(i0 + it * 4 + r) * 512 + j0 + jt * 4 + s] = c[r][s] + br[j0 + jt * 4 + s];
}

extern "C" void kernel_launch(void* const* d_in, const int* in_sizes, int n_in,
                              void* d_out, int out_size) {
    const float* x  = (const float*)d_in[0];
    const void*  ei = d_in[1];
    const float* W1 = (const float*)d_in[2];
    const float* b1 = (const float*)d_in[3];
    const float* W2 = (const float*)d_in[4];
    const float* b2 = (const float*)d_in[5];
    const float* W3 = (const float*)d_in[6];
    const float* b3 = (const float*)d_in[7];
    const float* W4 = (const float*)d_in[8];
    const float* b4 = (const float*)d_in[9];
    const float* Wr = (const float*)d_in[10];
    const float* br = (const float*)d_in[11];

    int E = in_sizes[1] / 2;
    if (E > EMAX) E = EMAX;

    float *pA1, *pB1, *pA2, *pB2, *ph1, *ph2;
    cudaGetSymbolAddress((void**)&pA1, g_A1);
    cudaGetSymbolAddress((void**)&pB1, g_B1);
    cudaGetSymbolAddress((void**)&pA2, g_A2);
    cudaGetSymbolAddress((void**)&pB2, g_B2);
    cudaGetSymbolAddress((void**)&ph1, g_h1);
    cudaGetSymbolAddress((void**)&ph2, g_h2);

    k_detect<<<1, 32>>>(ei);
    k_hist2<<<HB, 512>>>(ei, E);
    k_pre1<<<N, 64>>>(x, W1, b1);
    k_scanA<<<16, 64>>>();
    k_scanB<<<1, 1024>>>();
    k_scatter2<<<HB, 512>>>(ei, E);
    k_conv_mma<128, 4><<<N, 512>>>(pA1, pB1, W2, b2, ph1);
    k_pre2<<<N, 64>>>(W3, b3);
    k_conv_mma<512, 1><<<N, 512>>>(pA2, pB2, W4, b4, ph2);
    k_readout<<<dim3(8, 8), 256>>>(Wr, br, (float*)d_out);
}

// round 6
// speedup vs baseline: 4.9892x; 1.3391x over previous
#include <cuda_runtime.h>
#include <cstdint>

static constexpr int N    = 1024;
static constexpr int EMAX = 524288;
static constexpr int HB   = 256;   // histogram blocks

// ---------------- device scratch ----------------
__device__ int   g_is64;
__device__ int   g_bh[HB * N];
__device__ int   g_tot[N];
__device__ int   g_base[N];
__device__ int   g_off[N + 1];
__device__ int   g_src[EMAX];
__device__ float g_A1[N * 64];
__device__ float g_B1[N * 64];
__device__ float g_h1[N * 128];
__device__ float g_A2[N * 64];
__device__ float g_B2[N * 64];
__device__ float g_h2[N * 512];

__device__ __forceinline__ float neg_inf() { return __int_as_float(0xff800000); }

// pack two fp32 into fp16x2: lo -> low half, hi -> high half
__device__ __forceinline__ uint32_t pack_h2(float lo, float hi) {
    uint32_t r;
    asm("cvt.rn.f16x2.f32 %0, %1, %2;" : "=r"(r) : "f"(hi), "f"(lo));
    return r;
}

__device__ __forceinline__ void mma_f16(float d[4], const uint4& a,
                                        const uint32_t b[2]) {
    asm volatile(
        "mma.sync.aligned.m16n8k16.row.col.f32.f16.f16.f32 "
        "{%0,%1,%2,%3}, {%4,%5,%6,%7}, {%8,%9}, {%0,%1,%2,%3};"
        : "+f"(d[0]), "+f"(d[1]), "+f"(d[2]), "+f"(d[3])
        : "r"(a.x), "r"(a.y), "r"(a.z), "r"(a.w), "r"(b[0]), "r"(b[1]));
}

// ---------------- sort pipeline ----------------
__device__ __forceinline__ int edge_val(const void* p, long long i, int is64) {
    if (is64) return (int)((const long long*)p)[i];
    return ((const int*)p)[i];
}

__global__ void k_detect(const void* edges) {
    if (threadIdx.x == 0) {
        const long long* q = (const long long*)edges;
        int ok = 1;
        for (int i = 0; i < 64; i++) {
            long long v = q[i];
            if (v < 0 || v >= N) { ok = 0; break; }
        }
        g_is64 = ok;
    }
}

__global__ void k_hist2(const void* edges, int E) {
    __shared__ int h[N];
    int b = blockIdx.x, tid = threadIdx.x;
    for (int i = tid; i < N; i += 512) h[i] = 0;
    __syncthreads();
    int is64 = g_is64;
    int per = (E + HB - 1) / HB;
    int s0 = b * per, s1 = min(E, s0 + per);
    for (int base = s0; base < s1; base += 2048) {
        int d[4];
#pragma unroll
        for (int j = 0; j < 4; j++) {
            int e = base + tid + j * 512;
            d[j] = (e < s1) ? edge_val(edges, (long long)E + e, is64) : -1;
        }
#pragma unroll
        for (int j = 0; j < 4; j++)
            if (d[j] >= 0) atomicAdd(&h[d[j]], 1);
    }
    __syncthreads();
    for (int i = tid; i < N; i += 512) g_bh[b * N + i] = h[i];
}

// per-dst exclusive scan over the HB block-histograms (16 blocks x 64 dst)
__global__ void k_scanA() {
    int d = blockIdx.x * 64 + threadIdx.x;
    int tot = 0;
#pragma unroll 8
    for (int b = 0; b < HB; b++) {
        int t = g_bh[b * N + d];
        g_bh[b * N + d] = tot;
        tot += t;
    }
    g_tot[d] = tot;
}

// scan the per-dst totals over d (single block of N threads)
__global__ void k_scanB() {
    __shared__ int s[N];
    int d = threadIdx.x;
    int tot = g_tot[d];
    s[d] = tot;
    __syncthreads();
    for (int off = 1; off < N; off <<= 1) {
        int v = (d >= off) ? s[d - off] : 0;
        __syncthreads();
        s[d] += v;
        __syncthreads();
    }
    g_off[d + 1] = s[d];
    if (d == 0) g_off[0] = 0;
    g_base[d] = s[d] - tot;   // exclusive prefix for dst d
}

__global__ void k_scatter2(const void* edges, int E) {
    __shared__ int h[N];
    __shared__ int bhs[N];
    int b = blockIdx.x, tid = threadIdx.x;
    for (int i = tid; i < N; i += 512) {
        h[i] = 0;
        bhs[i] = g_base[i] + g_bh[b * N + i];
    }
    __syncthreads();
    int is64 = g_is64;
    int per = (E + HB - 1) / HB;
    int s0 = b * per, s1 = min(E, s0 + per);
    for (int base = s0; base < s1; base += 2048) {
        int d[4], sv[4];
#pragma unroll
        for (int j = 0; j < 4; j++) {
            int e = base + tid + j * 512;
            if (e < s1) {
                sv[j] = edge_val(edges, e, is64);
                d[j]  = edge_val(edges, (long long)E + e, is64);
            } else d[j] = -1;
        }
#pragma unroll
        for (int j = 0; j < 4; j++)
            if (d[j] >= 0) {
                int pos = bhs[d[j]] + atomicAdd(&h[d[j]], 1);
                g_src[pos] = sv[j];
            }
    }
}

// ---------------- per-node A/B precompute ----------------
__global__ void k_pre1(const float* __restrict__ x, const float* __restrict__ W1,
                       const float* __restrict__ b1) {
    __shared__ float xr[64];
    int n = blockIdx.x, j = threadIdx.x;
    xr[j] = x[n * 64 + j];
    __syncthreads();
    float a = b1[j], b = 0.f;
#pragma unroll 8
    for (int k = 0; k < 64; k++) {
        float xv = xr[k];
        a = fmaf(xv, W1[k * 64 + j], a);
        b = fmaf(xv, W1[(64 + k) * 64 + j], b);
    }
    g_A1[n * 64 + j] = a;
    g_B1[n * 64 + j] = b;
}

__global__ void k_pre2(const float* __restrict__ W3, const float* __restrict__ b3) {
    __shared__ float hr[128];
    int n = blockIdx.x, j = threadIdx.x;
    hr[j] = g_h1[n * 128 + j];
    hr[j + 64] = g_h1[n * 128 + j + 64];
    __syncthreads();
    float a = b3[j], b = 0.f;
#pragma unroll 8
    for (int k = 0; k < 128; k++) {
        float hv = hr[k];
        a = fmaf(hv, W3[k * 64 + j], a);
        b = fmaf(hv, W3[(128 + k) * 64 + j], b);
    }
    g_A2[n * 64 + j] = a;
    g_B2[n * 64 + j] = b;
}

// ---------------- tensor-core (mma.sync fp16 m16n8k16) EdgeConv ----------------
// One CTA per dst node, 512 threads = 16 warps.
// P tile (128 edges x 64 k, fp16) fragment-major:
//   uint4 slot [(m*32+L)*4 + ((s+(L>>1))&3)] = lane L's m16n8k16 A-fragment
//   for k-chunk s (16 wide): {a0,a1,a2,a3} with
//   a0 = P[m16+g][16s+2t .. +1], a1 = rows +8, a2 = cols +8, a3 = rows+cols +8
//   (g=L>>2, t=L&3). Rotation => conflict-free STS.128 / LDS.128.
// W fragments (B operand) in registers.
// m16n8k16 fp16 layout (PTX ISA):
//   B: b0 = {W[16s+2t][c], W[16s+2t+1][c]}, b1 = rows +8
//   D: d0=[g,2t] d1=[g,2t+1] d2=[g+8,2t] d3=[g+8,2t+1]
template <int C_OUT, int EG>
__global__ void __launch_bounds__(512, 1)
k_conv_mma(const float* __restrict__ Avec, const float* __restrict__ Bvec,
           const float* __restrict__ W, const float* __restrict__ bias,
           float* __restrict__ out) {
    constexpr int CG = 16 / EG;
    constexpr int NT = (C_OUT / CG) / 8;
    __shared__ __align__(16) uint4 Ps4[1024];
    __shared__ __align__(16) float avs[64];
    __shared__ float red[EG * C_OUT];
    __shared__ int srcs[2][128];

    int tid = threadIdx.x, lane = tid & 31;
    int wid = tid >> 5;
    int g = lane >> 2, tig = lane & 3;
    int cgrp = wid / EG, egrp = wid % EG;
    int cbase = cgrp * (NT * 8);
    int n = blockIdx.x;

    if (tid < 64) avs[tid] = Avec[n * 64 + tid];

    // W fragments (B operand), fp16x2 packed
    uint32_t wf[4][NT][2];
#pragma unroll
    for (int s = 0; s < 4; s++)
#pragma unroll
        for (int t = 0; t < NT; t++) {
            int c = cbase + t * 8 + g;
            int k0 = s * 16 + 2 * tig;
            wf[s][t][0] = pack_h2(W[k0 * C_OUT + c], W[(k0 + 1) * C_OUT + c]);
            wf[s][t][1] = pack_h2(W[(k0 + 8) * C_OUT + c], W[(k0 + 9) * C_OUT + c]);
        }

    float mx[NT][2];
#pragma unroll
    for (int t = 0; t < NT; t++) { mx[t][0] = neg_inf(); mx[t][1] = neg_inf(); }

    int beg = g_off[n], end = g_off[n + 1];
    if (tid < 128) srcs[0][tid] = (beg + tid < end) ? g_src[beg + tid] : 0;
    __syncthreads();

    int buf = 0;
    for (int t0 = beg; t0 < end; t0 += 128, buf ^= 1) {
        int cnt = min(128, end - t0);
        // --- build P tile, fragment-major fp16 ---
#pragma unroll
        for (int it = 0; it < 2; it++) {
            int idx = tid + it * 512;
            int m = idx >> 7, s = (idx >> 5) & 3, L = idx & 31;
            if (m * 16 < cnt) {
                int gg = L >> 2, tt = L & 3;
                int e0 = m * 16 + gg;
                int k0 = s * 16 + 2 * tt;
                const float* B0 = Bvec + srcs[buf][e0] * 64;
                const float* B1 = Bvec + srcs[buf][e0 + 8] * 64;
                float2 a0 = *(const float2*)(avs + k0);
                float2 a1 = *(const float2*)(avs + k0 + 8);
                float2 p0 = *(const float2*)(B0 + k0);
                float2 p1 = *(const float2*)(B1 + k0);
                float2 q0 = *(const float2*)(B0 + k0 + 8);
                float2 q1 = *(const float2*)(B1 + k0 + 8);
                uint4 v;
                v.x = pack_h2(fmaxf(a0.x + p0.x, 0.f), fmaxf(a0.y + p0.y, 0.f));
                v.y = pack_h2(fmaxf(a0.x + p1.x, 0.f), fmaxf(a0.y + p1.y, 0.f));
                v.z = pack_h2(fmaxf(a1.x + q0.x, 0.f), fmaxf(a1.y + q0.y, 0.f));
                v.w = pack_h2(fmaxf(a1.x + q1.x, 0.f), fmaxf(a1.y + q1.y, 0.f));
                Ps4[(m * 32 + L) * 4 + ((s + (L >> 1)) & 3)] = v;
            }
        }
        __syncthreads();
        // --- compute ---
        for (int m = egrp; m < 8; m += EG) {
            if (m * 16 >= cnt) break;
            float acc4[NT][4];
#pragma unroll
            for (int t = 0; t < NT; t++) {
                acc4[t][0] = 0.f; acc4[t][1] = 0.f;
                acc4[t][2] = 0.f; acc4[t][3] = 0.f;
            }
#pragma unroll
            for (int s = 0; s < 4; s++) {
                uint4 q = Ps4[(m * 32 + lane) * 4 + ((s + (lane >> 1)) & 3)];
#pragma unroll
                for (int t = 0; t < NT; t++) mma_f16(acc4[t], q, wf[s][t]);
            }
            int r0 = m * 16 + g;
            bool v0 = r0 < cnt, v1 = (r0 + 8) < cnt;
#pragma unroll
            for (int t = 0; t < NT; t++) {
                if (v0) { mx[t][0] = fmaxf(mx[t][0], acc4[t][0]);
                          mx[t][1] = fmaxf(mx[t][1], acc4[t][1]); }
                if (v1) { mx[t][0] = fmaxf(mx[t][0], acc4[t][2]);
                          mx[t][1] = fmaxf(mx[t][1], acc4[t][3]); }
            }
        }
        // prefetch next tile's src indices
        int nt0 = t0 + 128;
        if (tid < 128 && nt0 < end)
            srcs[buf ^ 1][tid] = (nt0 + tid < end) ? g_src[nt0 + tid] : 0;
        __syncthreads();
    }

    // reduce across the 8 row-groups (lanes stride 4, same tig)
#pragma unroll
    for (int t = 0; t < NT; t++)
#pragma unroll
        for (int off = 4; off < 32; off <<= 1) {
            mx[t][0] = fmaxf(mx[t][0], __shfl_xor_sync(0xffffffffu, mx[t][0], off));
            mx[t][1] = fmaxf(mx[t][1], __shfl_xor_sync(0xffffffffu, mx[t][1], off));
        }

    if (EG == 1) {
        if (lane < 4) {
#pragma unroll
            for (int t = 0; t < NT; t++) {
                int c = cbase + t * 8 + 2 * tig;
                float v0 = mx[t][0], v1 = mx[t][1];
                out[n * C_OUT + c]     = (v0 == neg_inf()) ? 0.f : v0 + bias[c];
                out[n * C_OUT + c + 1] = (v1 == neg_inf()) ? 0.f : v1 + bias[c + 1];
            }
        }
    } else {
        if (lane < 4) {
#pragma unroll
            for (int t = 0; t < NT; t++) {
                int c = cbase + t * 8 + 2 * tig;
                red[egrp * C_OUT + c]     = mx[t][0];
                red[egrp * C_OUT + c + 1] = mx[t][1];
            }
        }
        __syncthreads();
        for (int c = tid; c < C_OUT; c += 512) {
            float m = red[c];
#pragma unroll
            for (int e = 1; e < EG; e++) m = fmaxf(m, red[e * C_OUT + c]);
            out[n * C_OUT + c] = (m == neg_inf()) ? 0.f : m + bias[c];
        }
    }
}

// ---------------- readout: out[i][j] = sum_n h2[n][i]*Wr[n][j] + br[j] ----------
__global__ void k_readout(const float* __restrict__ Wr, const float* __restrict__ br,
                          float* __restrict__ out) {
    __shared__ float As[16][64];
    __shared__ float Bs[16][64];
    int i0 = blockIdx.y * 64, j0 = blockIdx.x * 64;
    int tid = threadIdx.x;
    int jt = tid & 15, it = tid >> 4;
    float c[4][4];
#pragma unroll
    for (int r = 0; r < 4; r++)
#pragma unroll
        for (int s = 0; s < 4; s++) c[r][s] = 0.f;

    for (int n0 = 0; n0 < N; n0 += 16) {
        for (int idx = tid; idx < 16 * 64; idx += 256) {
            int kk = idx >> 6, col = idx & 63;
            As[kk][col] = g_h2[(n0 + kk) * 512 + i0 + col];
            Bs[kk][col] = Wr[(n0 + kk) * 512 + j0 + col];
        }
        __syncthreads();
#pragma unroll
        for (int kk = 0; kk < 16; kk++) {
            float a[4], b[4];
#pragma unroll
            for (int r = 0; r < 4; r++) a[r] = As[kk][it * 4 + r];
#pragma unroll
            for (int s = 0; s < 4; s++) b[s] = Bs[kk][jt * 4 + s];
#pragma unroll
            for (int r = 0; r < 4; r++)
#pragma unroll
                for (int s = 0; s < 4; s++) c[r][s] = fmaf(a[r], b[s], c[r][s]);
        }
        __syncthreads();
    }
#pragma unroll
    for (int r = 0; r < 4; r++)
#pragma unroll
        for (int s = 0; s < 4; s++)
            out[(i0 + it * 4 + r) * 512 + j0 + jt * 4 + s] = c[r][s] + br[j0 + jt * 4 + s];
}

extern "C" void kernel_launch(void* const* d_in, const int* in_sizes, int n_in,
                              void* d_out, int out_size) {
    const float* x  = (const float*)d_in[0];
    const void*  ei = d_in[1];
    const float* W1 = (const float*)d_in[2];
    const float* b1 = (const float*)d_in[3];
    const float* W2 = (const float*)d_in[4];
    const float* b2 = (const float*)d_in[5];
    const float* W3 = (const float*)d_in[6];
    const float* b3 = (const float*)d_in[7];
    const float* W4 = (const float*)d_in[8];
    const float* b4 = (const float*)d_in[9];
    const float* Wr = (const float*)d_in[10];
    const float* br = (const float*)d_in[11];

    int E = in_sizes[1] / 2;
    if (E > EMAX) E = EMAX;

    float *pA1, *pB1, *pA2, *pB2, *ph1, *ph2;
    cudaGetSymbolAddress((void**)&pA1, g_A1);
    cudaGetSymbolAddress((void**)&pB1, g_B1);
    cudaGetSymbolAddress((void**)&pA2, g_A2);
    cudaGetSymbolAddress((void**)&pB2, g_B2);
    cudaGetSymbolAddress((void**)&ph1, g_h1);
    cudaGetSymbolAddress((void**)&ph2, g_h2);

    k_detect<<<1, 32>>>(ei);
    k_hist2<<<HB, 512>>>(ei, E);
    k_pre1<<<N, 64>>>(x, W1, b1);
    k_scanA<<<16, 64>>>();
    k_scanB<<<1, 1024>>>();
    k_scatter2<<<HB, 512>>>(ei, E);
    k_conv_mma<128, 4><<<N, 512>>>(pA1, pB1, W2, b2, ph1);
    k_pre2<<<N, 64>>>(W3, b3);
    k_conv_mma<512, 1><<<N, 512>>>(pA2, pB2, W4, b4, ph2);
    k_readout<<<dim3(8, 8), 256>>>(Wr, br, (float*)d_out);
}